// round 3
// baseline (speedup 1.0000x reference)
#include <cuda_runtime.h>
#include <cuda_bf16.h>
#include <cstdint>

// ---------------- problem constants ----------------
#define BSZ        4
#define DIM        512
#define D_INNER    1024
#define HEADDIM    128
#define NHEADS     8
#define D_STATE    128
#define D_CONV     4
#define CONV_DIM   1280          // D_INNER + 2*D_STATE
#define D_IN_PROJ  2312          // 2*D_INNER + 2*D_STATE + NHEADS
#define LSEQ       4096          // 16*16*16
#define NBL        (BSZ * LSEQ)  // 16384 rows (b,l)

// ---------------- device scratch (static globals; no allocation) ----------------
__device__ __align__(128) float  g_zx  [(size_t)NBL * D_IN_PROJ];   // in_proj out (z | xBC | dt_raw)
__device__ __align__(128) float  g_conv[(size_t)NBL * CONV_DIM];    // conv+silu out (xs | B | C)
__device__ __align__(128) float2 g_dtdA[NBL * NHEADS];              // (dt, exp(dt*A)) packed
__device__ __align__(128) float  g_y   [(size_t)NBL * D_INNER];     // scan out, normed in-place

// ---------------- f32x2 packed helpers ----------------
__device__ __forceinline__ uint64_t pack2(float lo, float hi) {
    uint64_t r; asm("mov.b64 %0, {%1, %2};" : "=l"(r) : "f"(lo), "f"(hi)); return r;
}
__device__ __forceinline__ void unpack2(uint64_t v, float& lo, float& hi) {
    asm("mov.b64 {%0, %1}, %2;" : "=f"(lo), "=f"(hi) : "l"(v));
}
__device__ __forceinline__ uint64_t fma2(uint64_t a, uint64_t b, uint64_t c) {
    uint64_t d; asm("fma.rn.f32x2 %0, %1, %2, %3;" : "=l"(d) : "l"(a), "l"(b), "l"(c)); return d;
}
__device__ __forceinline__ uint64_t mul2(uint64_t a, uint64_t b) {
    uint64_t d; asm("mul.rn.f32x2 %0, %1, %2;" : "=l"(d) : "l"(a), "l"(b)); return d;
}

// =====================================================================
// GEMM1: zxbcdt[m][n] = sum_k x[b][k][l] * W[n][k],  m = b*4096 + l
// M=16384, N=2312, K=512.  128x128x8 tile, 256 threads, 8x8 microtile.
// =====================================================================
__global__ __launch_bounds__(256) void gemm1_kernel(const float* __restrict__ x,
                                                    const float* __restrict__ W) {
    __shared__ float As[8][128];    // [k][m]
    __shared__ float Bs[8][132];    // [k][n] (padded)
    const int tid = threadIdx.x;
    const int m0  = blockIdx.y * 128;
    const int n0  = blockIdx.x * 128;
    const int b   = m0 >> 12;
    const int l0  = m0 & 4095;
    const float* Ap = x + (size_t)b * DIM * LSEQ + l0;   // + k*4096 + m_local

    const int tx = tid & 15, ty = tid >> 4;
    const int ka = tid >> 5;            // 0..7
    const int ma = (tid & 31) * 4;      // 0..124
    const int nb = tid >> 1;            // 0..127
    const int kb = (tid & 1) * 4;       // 0 or 4

    const int nglob = n0 + nb;
    const bool nval = (nglob < D_IN_PROJ);

    float acc[8][8];
#pragma unroll
    for (int i = 0; i < 8; i++)
#pragma unroll
        for (int j = 0; j < 8; j++) acc[i][j] = 0.f;

    for (int k0 = 0; k0 < DIM; k0 += 8) {
        float4 av = *(const float4*)(Ap + (size_t)(k0 + ka) * LSEQ + ma);
        float4 bv = make_float4(0.f, 0.f, 0.f, 0.f);
        if (nval) bv = *(const float4*)(W + (size_t)nglob * DIM + k0 + kb);
        *(float4*)&As[ka][ma] = av;
        Bs[kb + 0][nb] = bv.x; Bs[kb + 1][nb] = bv.y;
        Bs[kb + 2][nb] = bv.z; Bs[kb + 3][nb] = bv.w;
        __syncthreads();
#pragma unroll
        for (int kk = 0; kk < 8; kk++) {
            float a[8], bb[8];
            *(float4*)&a[0]  = *(float4*)&As[kk][ty * 8];
            *(float4*)&a[4]  = *(float4*)&As[kk][ty * 8 + 4];
            *(float4*)&bb[0] = *(float4*)&Bs[kk][tx * 8];
            *(float4*)&bb[4] = *(float4*)&Bs[kk][tx * 8 + 4];
#pragma unroll
            for (int i = 0; i < 8; i++)
#pragma unroll
                for (int j = 0; j < 8; j++)
                    acc[i][j] = fmaf(a[i], bb[j], acc[i][j]);
        }
        __syncthreads();
    }

    const bool full = (n0 + 128 <= D_IN_PROJ);
#pragma unroll
    for (int i = 0; i < 8; i++) {
        const int m = m0 + ty * 8 + i;
        float* op = g_zx + (size_t)m * D_IN_PROJ + n0 + tx * 8;
        if (full) {
            *(float4*)op       = make_float4(acc[i][0], acc[i][1], acc[i][2], acc[i][3]);
            *(float4*)(op + 4) = make_float4(acc[i][4], acc[i][5], acc[i][6], acc[i][7]);
        } else {
#pragma unroll
            for (int j = 0; j < 8; j++)
                if (n0 + tx * 8 + j < D_IN_PROJ) op[j] = acc[i][j];
        }
    }
}

// =====================================================================
// prep: dt = softplus(dt_raw + dt_bias); dA = exp(dt * (-exp(A_log)))
// packed into g_dtdA as (dt, dA)
// =====================================================================
__global__ __launch_bounds__(256) void prep_kernel(const float* __restrict__ dt_bias,
                                                   const float* __restrict__ A_log) {
    const int gid = blockIdx.x * 256 + threadIdx.x;   // < NBL*NHEADS = 131072
    const int bl = gid >> 3, h = gid & 7;
    float v = g_zx[(size_t)bl * D_IN_PROJ + (D_INNER + CONV_DIM) + h] + dt_bias[h];
    float dt = (v > 20.f) ? v : log1pf(expf(v));
    float A = -expf(A_log[h]);
    g_dtdA[gid] = make_float2(dt, expf(dt * A));
}

// =====================================================================
// conv: causal depthwise conv over l (width 4) + bias, then SiLU.
// =====================================================================
__global__ __launch_bounds__(256) void conv_kernel(const float* __restrict__ conv_w,
                                                   const float* __restrict__ conv_b) {
    const int gid = blockIdx.x * 256 + threadIdx.x;   // exactly NBL*CONV_DIM
    const int bl = gid / CONV_DIM;
    const int c  = gid - bl * CONV_DIM;
    const int l  = bl & 4095;
    const float w0 = conv_w[c * 4 + 0], w1 = conv_w[c * 4 + 1];
    const float w2 = conv_w[c * 4 + 2], w3 = conv_w[c * 4 + 3];
    const float* base = g_zx + (size_t)bl * D_IN_PROJ + D_INNER + c;
    float acc = conv_b[c];
    if (l >= 3) {
        acc += base[-3 * D_IN_PROJ] * w0;
        acc += base[-2 * D_IN_PROJ] * w1;
        acc += base[-1 * D_IN_PROJ] * w2;
        acc += base[0] * w3;
    } else {
        if (l >= 2) acc += base[-2 * D_IN_PROJ] * w1;
        if (l >= 1) acc += base[-1 * D_IN_PROJ] * w2;
        acc += base[0] * w3;
    }
    g_conv[gid] = acc / (1.f + expf(-acc));
}

// =====================================================================
// scan v2: register-resident, f32x2 packed, no smem, no syncthreads.
// 256 blocks = (b:4, h:8, ptile:8 of 16 rows). 256 threads = 8 warps.
// Thread layout: warp w covers p rows {2w, 2w+1}; lanes 0-15 -> row 2w,
// lanes 16-31 -> row 2w+1. Each lane owns n-slice [lane16*8, lane16*8+8)
// as 4 packed f32x2 states. y reduced over 16 lanes (4 bfly shuffles).
// B/C read directly from gmem as ulonglong2 (pre-packed), 2-step prefetch.
// =====================================================================
#define SCAN_LD(buf, t) do {                                                  \
    const float* _br = Bp + (size_t)(t) * CONV_DIM;                           \
    B##buf##a = *(const ulonglong2*)_br;                                      \
    B##buf##b = *(const ulonglong2*)(_br + 4);                                \
    C##buf##a = *(const ulonglong2*)(_br + D_STATE);                          \
    C##buf##b = *(const ulonglong2*)(_br + D_STATE + 4);                      \
    x##buf  = Xp[(size_t)(t) * CONV_DIM];                                     \
    dd##buf = DDp[(t) * NHEADS];                                              \
} while (0)

#define SCAN_STEP(buf, t) do {                                                \
    const float _dtx = x##buf * dd##buf.x;                                    \
    const uint64_t _dA2  = pack2(dd##buf.y, dd##buf.y);                       \
    const uint64_t _dtx2 = pack2(_dtx, _dtx);                                 \
    s0 = fma2(B##buf##a.x, _dtx2, mul2(s0, _dA2));                            \
    s1 = fma2(B##buf##a.y, _dtx2, mul2(s1, _dA2));                            \
    s2 = fma2(B##buf##b.x, _dtx2, mul2(s2, _dA2));                            \
    s3 = fma2(B##buf##b.y, _dtx2, mul2(s3, _dA2));                            \
    uint64_t _y2 = mul2(s0, C##buf##a.x);                                     \
    _y2 = fma2(s1, C##buf##a.y, _y2);                                         \
    _y2 = fma2(s2, C##buf##b.x, _y2);                                         \
    _y2 = fma2(s3, C##buf##b.y, _y2);                                         \
    float _ylo, _yhi; unpack2(_y2, _ylo, _yhi);                               \
    float _y = _ylo + _yhi;                                                   \
    _y += __shfl_xor_sync(0xffffffffu, _y, 8);                                \
    _y += __shfl_xor_sync(0xffffffffu, _y, 4);                                \
    _y += __shfl_xor_sync(0xffffffffu, _y, 2);                                \
    _y += __shfl_xor_sync(0xffffffffu, _y, 1);                                \
    if (lane16 == 0) Yp[(size_t)(t) * D_INNER] = _y + Dh * x##buf;            \
} while (0)

__global__ __launch_bounds__(256, 2) void scan_kernel(const float* __restrict__ D_param) {
    const int tid    = threadIdx.x;
    const int lane   = tid & 31;
    const int w      = tid >> 5;
    const int lane16 = lane & 15;
    const int bid = blockIdx.x;
    const int b  = bid >> 6;          // 64 blocks per batch (8 h * 8 ptiles)
    const int h  = (bid >> 3) & 7;
    const int pt = bid & 7;
    const int p  = pt * 16 + w * 2 + (lane >> 4);
    const int n0 = lane16 * 8;
    const float Dh = D_param[h];
    const int blbase = b << 12;

    const float* Bp = g_conv + (size_t)blbase * CONV_DIM + D_INNER + n0;
    const float* Xp = g_conv + (size_t)blbase * CONV_DIM + h * HEADDIM + p;
    const float2* DDp = g_dtdA + blbase * NHEADS + h;       // stride NHEADS per step
    float* Yp = g_y + (size_t)blbase * D_INNER + h * HEADDIM + p;

    uint64_t s0 = 0, s1 = 0, s2 = 0, s3 = 0;   // 8 n-states as 4 packed f32x2

    ulonglong2 B0a, B0b, C0a, C0b, B1a, B1b, C1a, C1b;
    float  x0, x1;
    float2 dd0, dd1;

    SCAN_LD(0, 0);
    SCAN_LD(1, 1);
    for (int t = 0; t < LSEQ; t += 2) {
        SCAN_STEP(0, t);
        SCAN_LD(0, min(t + 2, LSEQ - 1));
        SCAN_STEP(1, t + 1);
        SCAN_LD(1, min(t + 3, LSEQ - 1));
    }
}

// =====================================================================
// mulnorm: y = y * silu(z); y = y * rsqrt(mean(y^2)+1e-5) * norm_w
// =====================================================================
__global__ __launch_bounds__(256) void mulnorm_kernel(const float* __restrict__ norm_w) {
    __shared__ float red[8];
    __shared__ float rinv;
    const int bl = blockIdx.x, tid = threadIdx.x;
    const int lane = tid & 31, w = tid >> 5;
    float4 yv = *(const float4*)(g_y + (size_t)bl * D_INNER + tid * 4);
    float4 zv = *(const float4*)(g_zx + (size_t)bl * D_IN_PROJ + tid * 4);
    float4 t;
    t.x = yv.x * (zv.x / (1.f + expf(-zv.x)));
    t.y = yv.y * (zv.y / (1.f + expf(-zv.y)));
    t.z = yv.z * (zv.z / (1.f + expf(-zv.z)));
    t.w = yv.w * (zv.w / (1.f + expf(-zv.w)));
    float ss = t.x * t.x + t.y * t.y + t.z * t.z + t.w * t.w;
#pragma unroll
    for (int off = 16; off > 0; off >>= 1) ss += __shfl_xor_sync(0xffffffffu, ss, off);
    if (lane == 0) red[w] = ss;
    __syncthreads();
    if (tid == 0) {
        float tot = 0.f;
#pragma unroll
        for (int i = 0; i < 8; i++) tot += red[i];
        rinv = rsqrtf(tot * (1.f / (float)D_INNER) + 1e-5f);
    }
    __syncthreads();
    const float r = rinv;
    float4 w4 = *(const float4*)(norm_w + tid * 4);
    t.x *= r * w4.x; t.y *= r * w4.y; t.z *= r * w4.z; t.w *= r * w4.w;
    *(float4*)(g_y + (size_t)bl * D_INNER + tid * 4) = t;
}

// =====================================================================
// GEMM2: out[b][d][l] = sum_e Wo[d][e] * y[b*4096+l][e] + x[b][d][l]
// =====================================================================
__global__ __launch_bounds__(256) void gemm2_kernel(const float* __restrict__ Wo,
                                                    const float* __restrict__ x,
                                                    float* __restrict__ out) {
    __shared__ float As[8][132];   // [k][d]
    __shared__ float Bs[8][132];   // [k][l]
    const int tid = threadIdx.x;
    const int l0 = blockIdx.x * 128;
    const int d0 = blockIdx.y * 128;
    const int b  = blockIdx.z;
    const float* yp = g_y + (size_t)(b * LSEQ + l0) * D_INNER;

    const int tx = tid & 15, ty = tid >> 4;
    const int ra = tid >> 1;            // 0..127
    const int ka = (tid & 1) * 4;       // 0 or 4

    float acc[8][8];
#pragma unroll
    for (int i = 0; i < 8; i++)
#pragma unroll
        for (int j = 0; j < 8; j++) acc[i][j] = 0.f;

    for (int k0 = 0; k0 < D_INNER; k0 += 8) {
        float4 av = *(const float4*)(Wo + (size_t)(d0 + ra) * D_INNER + k0 + ka);
        float4 bv = *(const float4*)(yp + (size_t)ra * D_INNER + k0 + ka);
        As[ka + 0][ra] = av.x; As[ka + 1][ra] = av.y;
        As[ka + 2][ra] = av.z; As[ka + 3][ra] = av.w;
        Bs[ka + 0][ra] = bv.x; Bs[ka + 1][ra] = bv.y;
        Bs[ka + 2][ra] = bv.z; Bs[ka + 3][ra] = bv.w;
        __syncthreads();
#pragma unroll
        for (int kk = 0; kk < 8; kk++) {
            float a[8], bb[8];
            *(float4*)&a[0]  = *(float4*)&As[kk][ty * 8];
            *(float4*)&a[4]  = *(float4*)&As[kk][ty * 8 + 4];
            *(float4*)&bb[0] = *(float4*)&Bs[kk][tx * 8];
            *(float4*)&bb[4] = *(float4*)&Bs[kk][tx * 8 + 4];
#pragma unroll
            for (int i = 0; i < 8; i++)
#pragma unroll
                for (int j = 0; j < 8; j++)
                    acc[i][j] = fmaf(a[i], bb[j], acc[i][j]);
        }
        __syncthreads();
    }

    const size_t base = (size_t)b * DIM * LSEQ;
#pragma unroll
    for (int i = 0; i < 8; i++) {
        const int d = d0 + ty * 8 + i;
        const size_t off = base + (size_t)d * LSEQ + l0 + tx * 8;
        float4 x0 = *(const float4*)(x + off);
        float4 x1 = *(const float4*)(x + off + 4);
        float4 o0 = make_float4(acc[i][0] + x0.x, acc[i][1] + x0.y,
                                acc[i][2] + x0.z, acc[i][3] + x0.w);
        float4 o1 = make_float4(acc[i][4] + x1.x, acc[i][5] + x1.y,
                                acc[i][6] + x1.z, acc[i][7] + x1.w);
        *(float4*)(out + off)     = o0;
        *(float4*)(out + off + 4) = o1;
    }
}

// =====================================================================
extern "C" void kernel_launch(void* const* d_in, const int* in_sizes, int n_in,
                              void* d_out, int out_size) {
    const float* x          = (const float*)d_in[0];
    const float* in_proj_w  = (const float*)d_in[1];
    const float* conv_w     = (const float*)d_in[2];
    const float* conv_b     = (const float*)d_in[3];
    const float* dt_bias    = (const float*)d_in[4];
    const float* A_log      = (const float*)d_in[5];
    const float* D_param    = (const float*)d_in[6];
    const float* norm_w     = (const float*)d_in[7];
    const float* out_proj_w = (const float*)d_in[8];
    float* out = (float*)d_out;

    // 1. in_proj GEMM: (16384 x 512) @ (512 x 2312)
    gemm1_kernel<<<dim3((D_IN_PROJ + 127) / 128, NBL / 128), 256>>>(x, in_proj_w);
    // 2. dt softplus + dA packed
    prep_kernel<<<(NBL * NHEADS) / 256, 256>>>(dt_bias, A_log);
    // 3. depthwise causal conv + SiLU
    conv_kernel<<<((size_t)NBL * CONV_DIM) / 256, 256>>>(conv_w, conv_b);
    // 4. selective scan v2 (+ D skip)
    scan_kernel<<<BSZ * NHEADS * (HEADDIM / 16), 256>>>(D_param);
    // 5. gate + RMSNorm
    mulnorm_kernel<<<NBL, 256>>>(norm_w);
    // 6. out_proj GEMM + residual, transposed store
    gemm2_kernel<<<dim3(LSEQ / 128, DIM / 128, BSZ), 256>>>(out_proj_w, x, out);
}

// round 4
// speedup vs baseline: 1.7111x; 1.7111x over previous
#include <cuda_runtime.h>
#include <cuda_bf16.h>
#include <cstdint>

// ---------------- problem constants ----------------
#define BSZ        4
#define DIM        512
#define D_INNER    1024
#define HEADDIM    128
#define NHEADS     8
#define D_STATE    128
#define D_CONV     4
#define CONV_DIM   1280          // D_INNER + 2*D_STATE
#define D_IN_PROJ  2312          // 2*D_INNER + 2*D_STATE + NHEADS
#define LSEQ       4096          // 16*16*16
#define NBL        (BSZ * LSEQ)  // 16384 rows (b,l)

// ---------------- device scratch (static globals; no allocation) ----------------
__device__ __align__(128) float  g_zx  [(size_t)NBL * D_IN_PROJ];   // in_proj out (z | xBC | dt_raw)
__device__ __align__(128) float  g_conv[(size_t)NBL * CONV_DIM];    // conv+silu out (xs | B | C)
__device__ __align__(128) float2 g_dtdA[NBL * NHEADS];              // (dt, exp(dt*A)) packed
__device__ __align__(128) float  g_y   [(size_t)NBL * D_INNER];     // scan out, normed in-place

// ---------------- f32x2 packed helpers ----------------
__device__ __forceinline__ uint64_t pack2(float lo, float hi) {
    uint64_t r; asm("mov.b64 %0, {%1, %2};" : "=l"(r) : "f"(lo), "f"(hi)); return r;
}
__device__ __forceinline__ void unpack2(uint64_t v, float& lo, float& hi) {
    asm("mov.b64 {%0, %1}, %2;" : "=f"(lo), "=f"(hi) : "l"(v));
}
__device__ __forceinline__ uint64_t fma2(uint64_t a, uint64_t b, uint64_t c) {
    uint64_t d; asm("fma.rn.f32x2 %0, %1, %2, %3;" : "=l"(d) : "l"(a), "l"(b), "l"(c)); return d;
}
__device__ __forceinline__ uint64_t mul2(uint64_t a, uint64_t b) {
    uint64_t d; asm("mul.rn.f32x2 %0, %1, %2;" : "=l"(d) : "l"(a), "l"(b)); return d;
}

// =====================================================================
// GEMM1: zxbcdt[m][n] = sum_k x[b][k][l] * W[n][k],  m = b*4096 + l
// M=16384, N=2312, K=512.  128x128x8 tile, 256 threads, 8x8 microtile.
// =====================================================================
__global__ __launch_bounds__(256) void gemm1_kernel(const float* __restrict__ x,
                                                    const float* __restrict__ W) {
    __shared__ float As[8][128];    // [k][m]
    __shared__ float Bs[8][132];    // [k][n] (padded)
    const int tid = threadIdx.x;
    const int m0  = blockIdx.y * 128;
    const int n0  = blockIdx.x * 128;
    const int b   = m0 >> 12;
    const int l0  = m0 & 4095;
    const float* Ap = x + (size_t)b * DIM * LSEQ + l0;   // + k*4096 + m_local

    const int tx = tid & 15, ty = tid >> 4;
    const int ka = tid >> 5;            // 0..7
    const int ma = (tid & 31) * 4;      // 0..124
    const int nb = tid >> 1;            // 0..127
    const int kb = (tid & 1) * 4;       // 0 or 4

    const int nglob = n0 + nb;
    const bool nval = (nglob < D_IN_PROJ);

    float acc[8][8];
#pragma unroll
    for (int i = 0; i < 8; i++)
#pragma unroll
        for (int j = 0; j < 8; j++) acc[i][j] = 0.f;

    for (int k0 = 0; k0 < DIM; k0 += 8) {
        float4 av = *(const float4*)(Ap + (size_t)(k0 + ka) * LSEQ + ma);
        float4 bv = make_float4(0.f, 0.f, 0.f, 0.f);
        if (nval) bv = *(const float4*)(W + (size_t)nglob * DIM + k0 + kb);
        *(float4*)&As[ka][ma] = av;
        Bs[kb + 0][nb] = bv.x; Bs[kb + 1][nb] = bv.y;
        Bs[kb + 2][nb] = bv.z; Bs[kb + 3][nb] = bv.w;
        __syncthreads();
#pragma unroll
        for (int kk = 0; kk < 8; kk++) {
            float a[8], bb[8];
            *(float4*)&a[0]  = *(float4*)&As[kk][ty * 8];
            *(float4*)&a[4]  = *(float4*)&As[kk][ty * 8 + 4];
            *(float4*)&bb[0] = *(float4*)&Bs[kk][tx * 8];
            *(float4*)&bb[4] = *(float4*)&Bs[kk][tx * 8 + 4];
#pragma unroll
            for (int i = 0; i < 8; i++)
#pragma unroll
                for (int j = 0; j < 8; j++)
                    acc[i][j] = fmaf(a[i], bb[j], acc[i][j]);
        }
        __syncthreads();
    }

    const bool full = (n0 + 128 <= D_IN_PROJ);
#pragma unroll
    for (int i = 0; i < 8; i++) {
        const int m = m0 + ty * 8 + i;
        float* op = g_zx + (size_t)m * D_IN_PROJ + n0 + tx * 8;
        if (full) {
            *(float4*)op       = make_float4(acc[i][0], acc[i][1], acc[i][2], acc[i][3]);
            *(float4*)(op + 4) = make_float4(acc[i][4], acc[i][5], acc[i][6], acc[i][7]);
        } else {
#pragma unroll
            for (int j = 0; j < 8; j++)
                if (n0 + tx * 8 + j < D_IN_PROJ) op[j] = acc[i][j];
        }
    }
}

// =====================================================================
// prep: dt = softplus(dt_raw + dt_bias); dA = exp(dt * (-exp(A_log)))
// packed into g_dtdA as (dt, dA)
// =====================================================================
__global__ __launch_bounds__(256) void prep_kernel(const float* __restrict__ dt_bias,
                                                   const float* __restrict__ A_log) {
    const int gid = blockIdx.x * 256 + threadIdx.x;   // < NBL*NHEADS = 131072
    const int bl = gid >> 3, h = gid & 7;
    float v = g_zx[(size_t)bl * D_IN_PROJ + (D_INNER + CONV_DIM) + h] + dt_bias[h];
    float dt = (v > 20.f) ? v : log1pf(expf(v));
    float A = -expf(A_log[h]);
    g_dtdA[gid] = make_float2(dt, expf(dt * A));
}

// =====================================================================
// conv: causal depthwise conv over l (width 4) + bias, then SiLU.
// =====================================================================
__global__ __launch_bounds__(256) void conv_kernel(const float* __restrict__ conv_w,
                                                   const float* __restrict__ conv_b) {
    const int gid = blockIdx.x * 256 + threadIdx.x;   // exactly NBL*CONV_DIM
    const int bl = gid / CONV_DIM;
    const int c  = gid - bl * CONV_DIM;
    const int l  = bl & 4095;
    const float w0 = conv_w[c * 4 + 0], w1 = conv_w[c * 4 + 1];
    const float w2 = conv_w[c * 4 + 2], w3 = conv_w[c * 4 + 3];
    const float* base = g_zx + (size_t)bl * D_IN_PROJ + D_INNER + c;
    float acc = conv_b[c];
    if (l >= 3) {
        acc += base[-3 * D_IN_PROJ] * w0;
        acc += base[-2 * D_IN_PROJ] * w1;
        acc += base[-1 * D_IN_PROJ] * w2;
        acc += base[0] * w3;
    } else {
        if (l >= 2) acc += base[-2 * D_IN_PROJ] * w1;
        if (l >= 1) acc += base[-1 * D_IN_PROJ] * w2;
        acc += base[0] * w3;
    }
    g_conv[gid] = acc / (1.f + expf(-acc));
}

// =====================================================================
// scan v3: register-resident, f32x2 packed, DEPTH-4 software pipeline.
// 256 blocks = (b:4, h:8, ptile:8 of 16 rows). 256 threads = 8 warps.
// Thread layout: warp w covers p rows {2w, 2w+1}; lanes 0-15 -> row 2w,
// lanes 16-31 -> row 2w+1. Each lane owns n-slice [lane16*8, lane16*8+8)
// as 4 packed f32x2 states. y reduced over 16 lanes (4 bfly shuffles).
// B/C read directly from gmem as ulonglong2 (pre-packed), 4-step prefetch
// to cover ~250cyc L2 latency (round-3 showed depth-2 left it exposed).
// =====================================================================
#define SCAN_LD(buf, t) do {                                                  \
    const float* _br = Bp + (size_t)(t) * CONV_DIM;                           \
    B##buf##a = *(const ulonglong2*)_br;                                      \
    B##buf##b = *(const ulonglong2*)(_br + 4);                                \
    C##buf##a = *(const ulonglong2*)(_br + D_STATE);                          \
    C##buf##b = *(const ulonglong2*)(_br + D_STATE + 4);                      \
    x##buf  = Xp[(size_t)(t) * CONV_DIM];                                     \
    dd##buf = DDp[(t) * NHEADS];                                              \
} while (0)

#define SCAN_STEP(buf, t) do {                                                \
    const float _dtx = x##buf * dd##buf.x;                                    \
    const uint64_t _dA2  = pack2(dd##buf.y, dd##buf.y);                       \
    const uint64_t _dtx2 = pack2(_dtx, _dtx);                                 \
    s0 = fma2(B##buf##a.x, _dtx2, mul2(s0, _dA2));                            \
    s1 = fma2(B##buf##a.y, _dtx2, mul2(s1, _dA2));                            \
    s2 = fma2(B##buf##b.x, _dtx2, mul2(s2, _dA2));                            \
    s3 = fma2(B##buf##b.y, _dtx2, mul2(s3, _dA2));                            \
    uint64_t _y2 = mul2(s0, C##buf##a.x);                                     \
    _y2 = fma2(s1, C##buf##a.y, _y2);                                         \
    _y2 = fma2(s2, C##buf##b.x, _y2);                                         \
    _y2 = fma2(s3, C##buf##b.y, _y2);                                         \
    float _ylo, _yhi; unpack2(_y2, _ylo, _yhi);                               \
    float _y = _ylo + _yhi;                                                   \
    _y += __shfl_xor_sync(0xffffffffu, _y, 8);                                \
    _y += __shfl_xor_sync(0xffffffffu, _y, 4);                                \
    _y += __shfl_xor_sync(0xffffffffu, _y, 2);                                \
    _y += __shfl_xor_sync(0xffffffffu, _y, 1);                                \
    if (lane16 == 0) Yp[(size_t)(t) * D_INNER] = _y + Dh * x##buf;            \
} while (0)

__global__ __launch_bounds__(256, 2) void scan_kernel(const float* __restrict__ D_param) {
    const int tid    = threadIdx.x;
    const int lane   = tid & 31;
    const int w      = tid >> 5;
    const int lane16 = lane & 15;
    const int bid = blockIdx.x;
    const int b  = bid >> 6;          // 64 blocks per batch (8 h * 8 ptiles)
    const int h  = (bid >> 3) & 7;
    const int pt = bid & 7;
    const int p  = pt * 16 + w * 2 + (lane >> 4);
    const int n0 = lane16 * 8;
    const float Dh = D_param[h];
    const int blbase = b << 12;

    const float* Bp = g_conv + (size_t)blbase * CONV_DIM + D_INNER + n0;
    const float* Xp = g_conv + (size_t)blbase * CONV_DIM + h * HEADDIM + p;
    const float2* DDp = g_dtdA + blbase * NHEADS + h;       // stride NHEADS per step
    float* Yp = g_y + (size_t)blbase * D_INNER + h * HEADDIM + p;

    uint64_t s0 = 0, s1 = 0, s2 = 0, s3 = 0;   // 8 n-states as 4 packed f32x2

    ulonglong2 B0a, B0b, C0a, C0b;
    ulonglong2 B1a, B1b, C1a, C1b;
    ulonglong2 B2a, B2b, C2a, C2b;
    ulonglong2 B3a, B3b, C3a, C3b;
    float  x0, x1, x2, x3;
    float2 dd0, dd1, dd2, dd3;

    SCAN_LD(0, 0);
    SCAN_LD(1, 1);
    SCAN_LD(2, 2);
    SCAN_LD(3, 3);
    for (int t = 0; t < LSEQ; t += 4) {
        SCAN_STEP(0, t);
        SCAN_LD(0, min(t + 4, LSEQ - 1));
        SCAN_STEP(1, t + 1);
        SCAN_LD(1, min(t + 5, LSEQ - 1));
        SCAN_STEP(2, t + 2);
        SCAN_LD(2, min(t + 6, LSEQ - 1));
        SCAN_STEP(3, t + 3);
        SCAN_LD(3, min(t + 7, LSEQ - 1));
    }
}

// =====================================================================
// mulnorm: y = y * silu(z); y = y * rsqrt(mean(y^2)+1e-5) * norm_w
// =====================================================================
__global__ __launch_bounds__(256) void mulnorm_kernel(const float* __restrict__ norm_w) {
    __shared__ float red[8];
    __shared__ float rinv;
    const int bl = blockIdx.x, tid = threadIdx.x;
    const int lane = tid & 31, w = tid >> 5;
    float4 yv = *(const float4*)(g_y + (size_t)bl * D_INNER + tid * 4);
    float4 zv = *(const float4*)(g_zx + (size_t)bl * D_IN_PROJ + tid * 4);
    float4 t;
    t.x = yv.x * (zv.x / (1.f + expf(-zv.x)));
    t.y = yv.y * (zv.y / (1.f + expf(-zv.y)));
    t.z = yv.z * (zv.z / (1.f + expf(-zv.z)));
    t.w = yv.w * (zv.w / (1.f + expf(-zv.w)));
    float ss = t.x * t.x + t.y * t.y + t.z * t.z + t.w * t.w;
#pragma unroll
    for (int off = 16; off > 0; off >>= 1) ss += __shfl_xor_sync(0xffffffffu, ss, off);
    if (lane == 0) red[w] = ss;
    __syncthreads();
    if (tid == 0) {
        float tot = 0.f;
#pragma unroll
        for (int i = 0; i < 8; i++) tot += red[i];
        rinv = rsqrtf(tot * (1.f / (float)D_INNER) + 1e-5f);
    }
    __syncthreads();
    const float r = rinv;
    float4 w4 = *(const float4*)(norm_w + tid * 4);
    t.x *= r * w4.x; t.y *= r * w4.y; t.z *= r * w4.z; t.w *= r * w4.w;
    *(float4*)(g_y + (size_t)bl * D_INNER + tid * 4) = t;
}

// =====================================================================
// GEMM2: out[b][d][l] = sum_e Wo[d][e] * y[b*4096+l][e] + x[b][d][l]
// =====================================================================
__global__ __launch_bounds__(256) void gemm2_kernel(const float* __restrict__ Wo,
                                                    const float* __restrict__ x,
                                                    float* __restrict__ out) {
    __shared__ float As[8][132];   // [k][d]
    __shared__ float Bs[8][132];   // [k][l]
    const int tid = threadIdx.x;
    const int l0 = blockIdx.x * 128;
    const int d0 = blockIdx.y * 128;
    const int b  = blockIdx.z;
    const float* yp = g_y + (size_t)(b * LSEQ + l0) * D_INNER;

    const int tx = tid & 15, ty = tid >> 4;
    const int ra = tid >> 1;            // 0..127
    const int ka = (tid & 1) * 4;       // 0 or 4

    float acc[8][8];
#pragma unroll
    for (int i = 0; i < 8; i++)
#pragma unroll
        for (int j = 0; j < 8; j++) acc[i][j] = 0.f;

    for (int k0 = 0; k0 < D_INNER; k0 += 8) {
        float4 av = *(const float4*)(Wo + (size_t)(d0 + ra) * D_INNER + k0 + ka);
        float4 bv = *(const float4*)(yp + (size_t)ra * D_INNER + k0 + ka);
        As[ka + 0][ra] = av.x; As[ka + 1][ra] = av.y;
        As[ka + 2][ra] = av.z; As[ka + 3][ra] = av.w;
        Bs[ka + 0][ra] = bv.x; Bs[ka + 1][ra] = bv.y;
        Bs[ka + 2][ra] = bv.z; Bs[ka + 3][ra] = bv.w;
        __syncthreads();
#pragma unroll
        for (int kk = 0; kk < 8; kk++) {
            float a[8], bb[8];
            *(float4*)&a[0]  = *(float4*)&As[kk][ty * 8];
            *(float4*)&a[4]  = *(float4*)&As[kk][ty * 8 + 4];
            *(float4*)&bb[0] = *(float4*)&Bs[kk][tx * 8];
            *(float4*)&bb[4] = *(float4*)&Bs[kk][tx * 8 + 4];
#pragma unroll
            for (int i = 0; i < 8; i++)
#pragma unroll
                for (int j = 0; j < 8; j++)
                    acc[i][j] = fmaf(a[i], bb[j], acc[i][j]);
        }
        __syncthreads();
    }

    const size_t base = (size_t)b * DIM * LSEQ;
#pragma unroll
    for (int i = 0; i < 8; i++) {
        const int d = d0 + ty * 8 + i;
        const size_t off = base + (size_t)d * LSEQ + l0 + tx * 8;
        float4 x0 = *(const float4*)(x + off);
        float4 x1 = *(const float4*)(x + off + 4);
        float4 o0 = make_float4(acc[i][0] + x0.x, acc[i][1] + x0.y,
                                acc[i][2] + x0.z, acc[i][3] + x0.w);
        float4 o1 = make_float4(acc[i][4] + x1.x, acc[i][5] + x1.y,
                                acc[i][6] + x1.z, acc[i][7] + x1.w);
        *(float4*)(out + off)     = o0;
        *(float4*)(out + off + 4) = o1;
    }
}

// =====================================================================
extern "C" void kernel_launch(void* const* d_in, const int* in_sizes, int n_in,
                              void* d_out, int out_size) {
    const float* x          = (const float*)d_in[0];
    const float* in_proj_w  = (const float*)d_in[1];
    const float* conv_w     = (const float*)d_in[2];
    const float* conv_b     = (const float*)d_in[3];
    const float* dt_bias    = (const float*)d_in[4];
    const float* A_log      = (const float*)d_in[5];
    const float* D_param    = (const float*)d_in[6];
    const float* norm_w     = (const float*)d_in[7];
    const float* out_proj_w = (const float*)d_in[8];
    float* out = (float*)d_out;

    // 1. in_proj GEMM: (16384 x 512) @ (512 x 2312)
    gemm1_kernel<<<dim3((D_IN_PROJ + 127) / 128, NBL / 128), 256>>>(x, in_proj_w);
    // 2. dt softplus + dA packed
    prep_kernel<<<(NBL * NHEADS) / 256, 256>>>(dt_bias, A_log);
    // 3. depthwise causal conv + SiLU
    conv_kernel<<<((size_t)NBL * CONV_DIM) / 256, 256>>>(conv_w, conv_b);
    // 4. selective scan v3 (+ D skip), depth-4 pipeline
    scan_kernel<<<BSZ * NHEADS * (HEADDIM / 16), 256>>>(D_param);
    // 5. gate + RMSNorm
    mulnorm_kernel<<<NBL, 256>>>(norm_w);
    // 6. out_proj GEMM + residual, transposed store
    gemm2_kernel<<<dim3(LSEQ / 128, DIM / 128, BSZ), 256>>>(out_proj_w, x, out);
}